// round 14
// baseline (speedup 1.0000x reference)
#include <cuda_runtime.h>
#include <cuda_bf16.h>
#include <mma.h>
#include <cstddef>
#include <cstdint>

using namespace nvcuda;

// Problem constants (fixed by setup_inputs)
constexpr int D      = 64;
constexpr int N      = 128;
constexpr int NSTEPS = 16;

constexpr int MROWS = D * D;       // 4096 = (i,a)
constexpr int NCOLS = N * D;       // 8192 = (n,b)

// ---------------- device scratch (no allocations allowed) ----------------
// Split-bf16 operands (a ~= a0 + a1, 16 effective mantissa bits)
__device__ __align__(16) __nv_bfloat16 g_A0[MROWS * NSTEPS];   // A[r][s], r=(i,a)
__device__ __align__(16) __nv_bfloat16 g_A1[MROWS * NSTEPS];
__device__ __align__(16) __nv_bfloat16 g_B0[NSTEPS * NCOLS];   // B[s][c], c=(n,b)
__device__ __align__(16) __nv_bfloat16 g_B1[NSTEPS * NCOLS];

__device__ __forceinline__ void bf16split(float f, __nv_bfloat16& h0,
                                          __nv_bfloat16& h1) {
    h0 = __float2bfloat16_rn(f);
    h1 = __float2bfloat16_rn(f - __bfloat162float(h0));
}

// KPREP: direct row-wise simulation, warp-per-row (syncwarp only — measured
// 2.5x faster than the 2-warps/row + __syncthreads variant).
//   rows 0..127   : state rows (x0, v0)  -> B splits + traj frames
//   rows 128..191 : propagator rows a: X0 = dt^2*e_a, V0 = dt*e_a -> A splits
// Lane owns 2 columns; M columns in registers.
// M[k][c] = W[c][k] - delta(k,c)  (row-vector convention: f = x*M).
__global__ void __launch_bounds__(128) kprep(const float* __restrict__ x0,
                                             const float* __restrict__ v0,
                                             const float* __restrict__ W,
                                             float* __restrict__ out) {
    __shared__ float sX[4][D];
    const int tid = threadIdx.x;
    const int w   = tid >> 5;                  // warp = local row
    const int l   = tid & 31;
    const int row = blockIdx.x * 4 + w;        // 0..191
    const int c0  = 2 * l;
    const float dt = 0.01f;
    const bool is_state = (row < N);
    const int a = row - N;

    float mA[D], mB[D];
    {
        const float4* wa = (const float4*)(W + (size_t)c0 * D);
        const float4* wb = (const float4*)(W + (size_t)(c0 + 1) * D);
#pragma unroll
        for (int q = 0; q < 16; q++) {
            float4 va = wa[q], vb = wb[q];
            const int k = 4 * q;
            mA[k+0] = va.x - ((k+0) == c0     ? 1.0f : 0.0f);
            mA[k+1] = va.y - ((k+1) == c0     ? 1.0f : 0.0f);
            mA[k+2] = va.z - ((k+2) == c0     ? 1.0f : 0.0f);
            mA[k+3] = va.w - ((k+3) == c0     ? 1.0f : 0.0f);
            mB[k+0] = vb.x - ((k+0) == c0 + 1 ? 1.0f : 0.0f);
            mB[k+1] = vb.y - ((k+1) == c0 + 1 ? 1.0f : 0.0f);
            mB[k+2] = vb.z - ((k+2) == c0 + 1 ? 1.0f : 0.0f);
            mB[k+3] = vb.w - ((k+3) == c0 + 1 ? 1.0f : 0.0f);
        }
    }

    float2 xl, vl;
    if (is_state) {
        xl = *(const float2*)(x0 + (size_t)row * D + c0);
        vl = *(const float2*)(v0 + (size_t)row * D + c0);
    } else {
        xl = make_float2(c0 == a ? dt * dt : 0.0f, (c0 + 1) == a ? dt * dt : 0.0f);
        vl = make_float2(c0 == a ? dt      : 0.0f, (c0 + 1) == a ? dt      : 0.0f);
    }

    // t = 0 outputs.
    if (is_state) {
        *(float2*)(out + (size_t)row * D + c0) = xl;          // traj frame 0
        __nv_bfloat16 h0, h1, g0, g1;
        bf16split(xl.x, h0, h1); bf16split(xl.y, g0, g1);
        *(__nv_bfloat162*)&g_B0[(size_t)row * D + c0] = {h0, g0};
        *(__nv_bfloat162*)&g_B1[(size_t)row * D + c0] = {h1, g1};
    } else {
        bf16split(xl.x, g_A0[((size_t)c0 * D + a) * NSTEPS + 15],
                        g_A1[((size_t)c0 * D + a) * NSTEPS + 15]);
        bf16split(xl.y, g_A0[((size_t)(c0 + 1) * D + a) * NSTEPS + 15],
                        g_A1[((size_t)(c0 + 1) * D + a) * NSTEPS + 15]);
    }

    *(float2*)&sX[w][c0] = xl;
    __syncwarp();

#pragma unroll 1
    for (int t = 1; t <= NSTEPS; t++) {
        float2 y0 = make_float2(0.0f, 0.0f);
        float2 y1 = make_float2(0.0f, 0.0f);
#pragma unroll
        for (int k = 0; k < D; k += 2) {
            float xk0 = sX[w][k], xk1 = sX[w][k + 1];
            y0.x += xk0 * mA[k];     y0.y += xk0 * mB[k];
            y1.x += xk1 * mA[k + 1]; y1.y += xk1 * mB[k + 1];
        }
        vl.x += dt * (y0.x + y1.x);  vl.y += dt * (y0.y + y1.y);
        xl.x += dt * vl.x;           xl.y += dt * vl.y;
        __syncwarp();
        *(float2*)&sX[w][c0] = xl;
        __syncwarp();

        if (is_state) {
            if (t < NSTEPS) {
                __nv_bfloat16 h0, h1, g0, g1;
                bf16split(xl.x, h0, h1); bf16split(xl.y, g0, g1);
                const size_t o = (size_t)t * NCOLS + (size_t)row * D + c0;
                *(__nv_bfloat162*)&g_B0[o] = {h0, g0};
                *(__nv_bfloat162*)&g_B1[o] = {h1, g1};
            }
            if ((t & 3) == 0) {
                float* o = out + (size_t)(t >> 2) * NCOLS + (size_t)row * D + c0;
                *(float2*)o = xl;
            }
        } else if (t < NSTEPS) {
            bf16split(xl.x, g_A0[((size_t)c0 * D + a) * NSTEPS + (15 - t)],
                            g_A1[((size_t)c0 * D + a) * NSTEPS + (15 - t)]);
            bf16split(xl.y, g_A0[((size_t)(c0 + 1) * D + a) * NSTEPS + (15 - t)],
                            g_A1[((size_t)(c0 + 1) * D + a) * NSTEPS + (15 - t)]);
        }
    }
}

// K4: C[(i,a)][(n,b)] = sum_s A[(i,a)][s] * B[s][(n,b)]  — one 4096x8192x16
// GEMM via wmma 16x16x16 bf16, 3-pass split-bf16 (a0b0 + a0b1 + a1b0).
// Block tile 128(M) x 128(N); 8 warps = 4M x 2N. Epilogue: each warp's 4 nt
// tiles (same n, b=0..63) are staged per-mt as a 16x64 f32 tile in a private
// smem buffer, then copied with fully-coalesced STG.128 (rows = 256 B lines)
// — replaces store_matrix_sync's 32 B-per-row scatter (~4x fewer store wf).
constexpr int ALD = 24;    // bf16 smem ldm for A (16 + 8 pad)
constexpr int BLD = 136;   // bf16 smem ldm for B (128 + 8 pad)
constexpr int CLD = 68;    // f32 smem ldm for C staging (64 + 4 pad)

__global__ void __launch_bounds__(256) k4_jac(float* __restrict__ jac) {
    __shared__ __align__(16) __nv_bfloat16 sA0[128 * ALD];   // 6 KB
    __shared__ __align__(16) __nv_bfloat16 sA1[128 * ALD];   // 6 KB
    __shared__ __align__(16) __nv_bfloat16 sB0[16 * BLD];    // 4.25 KB
    __shared__ __align__(16) __nv_bfloat16 sB1[16 * BLD];    // 4.25 KB
    __shared__ __align__(16) float sC[8][16 * CLD];          // 34 KB
    const int tid = threadIdx.x, bid = blockIdx.x;
    const int m0 = (bid & 31) * 128;   // 32 M-blocks
    const int n0 = (bid >> 5) * 128;   // 64 N-blocks

    // Stage A (128 rows x 16 bf16) and B (16 rows x 128 bf16), both splits.
    {
        const int row = tid >> 1, q = (tid & 1) << 3;
        *(float4*)&sA0[row * ALD + q] =
            *(const float4*)&g_A0[(size_t)(m0 + row) * NSTEPS + q];
        *(float4*)&sA1[row * ALD + q] =
            *(const float4*)&g_A1[(size_t)(m0 + row) * NSTEPS + q];
        const int s = tid >> 4, bq = (tid & 15) << 3;
        *(float4*)&sB0[s * BLD + bq] =
            *(const float4*)&g_B0[(size_t)s * NCOLS + n0 + bq];
        *(float4*)&sB1[s * BLD + bq] =
            *(const float4*)&g_B1[(size_t)s * NCOLS + n0 + bq];
    }
    __syncthreads();

    const int wid = tid >> 5, lane = tid & 31;
    const int wm = wid & 3, wn = wid >> 2;

    wmma::fragment<wmma::matrix_a, 16, 16, 16, __nv_bfloat16,
                   wmma::row_major> a0f[2], a1f[2];
#pragma unroll
    for (int mt = 0; mt < 2; mt++) {
        const int ro = (wm * 32 + mt * 16) * ALD;
        wmma::load_matrix_sync(a0f[mt], &sA0[ro], ALD);
        wmma::load_matrix_sync(a1f[mt], &sA1[ro], ALD);
    }
    wmma::fragment<wmma::matrix_b, 16, 16, 16, __nv_bfloat16,
                   wmma::row_major> b0f[4], b1f[4];
#pragma unroll
    for (int nt = 0; nt < 4; nt++) {
        const int cl = wn * 64 + nt * 16;
        wmma::load_matrix_sync(b0f[nt], &sB0[cl], BLD);
        wmma::load_matrix_sync(b1f[nt], &sB1[cl], BLD);
    }

    float* cbuf = sC[wid];
#pragma unroll
    for (int mt = 0; mt < 2; mt++) {
#pragma unroll
        for (int nt = 0; nt < 4; nt++) {
            wmma::fragment<wmma::accumulator, 16, 16, 16, float> acc;
            wmma::fill_fragment(acc, 0.0f);
            wmma::mma_sync(acc, a0f[mt], b0f[nt], acc);
            wmma::mma_sync(acc, a0f[mt], b1f[nt], acc);
            wmma::mma_sync(acc, a1f[mt], b0f[nt], acc);
            wmma::store_matrix_sync(&cbuf[nt * 16], acc, CLD,
                                    wmma::mem_row_major);
        }
        __syncwarp();
        // Copy 16 x 64 f32 tile -> jac, fully coalesced (rows = 256 B lines).
        const int r = m0 + wm * 32 + mt * 16;       // (i,a): i = r>>6, a = r&63
        const int c = n0 + wn * 64;                 // (n,b): b = 0 here
        float* dst = jac + (size_t)(c >> 6) * (64 * 64 * 64)
                   + (size_t)(r >> 6) * (64 * 64)
                   + (size_t)(r & 63) * 64;
#pragma unroll
        for (int it = 0; it < 8; it++) {
            const int idx = it * 32 + lane;         // 256 float4 chunks
            const int rr = idx >> 4, q = (idx & 15) << 2;
            *(float4*)&dst[(size_t)rr * 64 + q] = *(float4*)&cbuf[rr * CLD + q];
        }
        __syncwarp();
    }
}

extern "C" void kernel_launch(void* const* d_in, const int* in_sizes, int n_in,
                              void* d_out, int out_size) {
    const float* x0 = (const float*)d_in[0];
    const float* v0 = (const float*)d_in[1];
    const float* W  = (const float*)d_in[2];
    float* out = (float*)d_out;
    // output = [traj (frames x N x D)] then [jac (N x D x D x D)]
    float* jac = out + ((size_t)out_size - (size_t)N * D * D * D);

    kprep<<<48, 128>>>(x0, v0, W, out);
    k4_jac<<<2048, 256>>>(jac);
}

// round 15
// speedup vs baseline: 1.0968x; 1.0968x over previous
#include <cuda_runtime.h>
#include <cuda_bf16.h>
#include <mma.h>
#include <cstddef>
#include <cstdint>

using namespace nvcuda;

// Problem constants (fixed by setup_inputs)
constexpr int D      = 64;
constexpr int N      = 128;
constexpr int NSTEPS = 16;

constexpr int MROWS = D * D;       // 4096 = (i,a)
constexpr int NCOLS = N * D;       // 8192 = (n,b)

// ---------------- device scratch (no allocations allowed) ----------------
__device__ __align__(16) float g_R[NSTEPS][D * D];  // [s][i*64+a] = R_{15-s}[a][i]
__device__ __align__(16) float g_X[NSTEPS][N * D];  // x_s, s = 0..15
// Split-bf16 operands (a ~= a0 + a1, 16 effective mantissa bits)
__device__ __align__(16) __nv_bfloat16 g_A0[MROWS * NSTEPS];   // A[r][s], r=(i,a)
__device__ __align__(16) __nv_bfloat16 g_A1[MROWS * NSTEPS];
__device__ __align__(16) __nv_bfloat16 g_B0[NSTEPS * NCOLS];   // B[s][c], c=(n,b)
__device__ __align__(16) __nv_bfloat16 g_B1[NSTEPS * NCOLS];

// KPREP: direct row-wise simulation of BOTH systems (floats only — the
// bf16 splitting lives in ksplit; fusing it here measured 3x slower).
//   rows 0..127   : state rows (x0, v0)            -> g_X[t], traj frames
//   rows 128..191 : propagator rows a = row-128,
//                   X0 = dt^2*e_a, V0 = dt*e_a     -> g_R (transposed)
// One warp per row; lane owns 2 columns; M columns in registers.
// M[k][c] = W[c][k] - delta(k,c)  (row-vector convention: f = x*M).
__global__ void __launch_bounds__(128) kprep(const float* __restrict__ x0,
                                             const float* __restrict__ v0,
                                             const float* __restrict__ W,
                                             float* __restrict__ out) {
    __shared__ float sX[4][D];
    const int tid = threadIdx.x;
    const int w   = tid >> 5;                  // warp = local row
    const int l   = tid & 31;
    const int row = blockIdx.x * 4 + w;        // 0..191
    const int c0  = 2 * l;
    const float dt = 0.01f;
    const bool is_state = (row < N);
    const int a = row - N;

    float mA[D], mB[D];
    {
        const float4* wa = (const float4*)(W + (size_t)c0 * D);
        const float4* wb = (const float4*)(W + (size_t)(c0 + 1) * D);
#pragma unroll
        for (int q = 0; q < 16; q++) {
            float4 va = wa[q], vb = wb[q];
            const int k = 4 * q;
            mA[k+0] = va.x - ((k+0) == c0     ? 1.0f : 0.0f);
            mA[k+1] = va.y - ((k+1) == c0     ? 1.0f : 0.0f);
            mA[k+2] = va.z - ((k+2) == c0     ? 1.0f : 0.0f);
            mA[k+3] = va.w - ((k+3) == c0     ? 1.0f : 0.0f);
            mB[k+0] = vb.x - ((k+0) == c0 + 1 ? 1.0f : 0.0f);
            mB[k+1] = vb.y - ((k+1) == c0 + 1 ? 1.0f : 0.0f);
            mB[k+2] = vb.z - ((k+2) == c0 + 1 ? 1.0f : 0.0f);
            mB[k+3] = vb.w - ((k+3) == c0 + 1 ? 1.0f : 0.0f);
        }
    }

    float2 xl, vl;
    if (is_state) {
        xl = *(const float2*)(x0 + (size_t)row * D + c0);
        vl = *(const float2*)(v0 + (size_t)row * D + c0);
    } else {
        xl = make_float2(c0 == a ? dt * dt : 0.0f, (c0 + 1) == a ? dt * dt : 0.0f);
        vl = make_float2(c0 == a ? dt      : 0.0f, (c0 + 1) == a ? dt      : 0.0f);
    }

    // t = 0 outputs.
    if (is_state) {
        *(float2*)&g_X[0][row * D + c0] = xl;                 // x_0
        *(float2*)(out + (size_t)row * D + c0) = xl;          // traj frame 0
    } else {
        g_R[15][c0 * D + a]       = xl.x;                     // R_0 transposed
        g_R[15][(c0 + 1) * D + a] = xl.y;
    }

    *(float2*)&sX[w][c0] = xl;
    __syncwarp();

#pragma unroll 1
    for (int t = 1; t <= NSTEPS; t++) {
        float2 y0 = make_float2(0.0f, 0.0f);
        float2 y1 = make_float2(0.0f, 0.0f);
#pragma unroll
        for (int k = 0; k < D; k += 2) {
            float xk0 = sX[w][k], xk1 = sX[w][k + 1];
            y0.x += xk0 * mA[k];     y0.y += xk0 * mB[k];
            y1.x += xk1 * mA[k + 1]; y1.y += xk1 * mB[k + 1];
        }
        vl.x += dt * (y0.x + y1.x);  vl.y += dt * (y0.y + y1.y);
        xl.x += dt * vl.x;           xl.y += dt * vl.y;
        __syncwarp();
        *(float2*)&sX[w][c0] = xl;
        __syncwarp();

        if (is_state) {
            if (t < NSTEPS)
                *(float2*)&g_X[t][row * D + c0] = xl;
            if ((t & 3) == 0) {
                float* o = out + (size_t)(t >> 2) * NCOLS + (size_t)row * D + c0;
                *(float2*)o = xl;
            }
        } else if (t < NSTEPS) {
            g_R[15 - t][c0 * D + a]       = xl.x;
            g_R[15 - t][(c0 + 1) * D + a] = xl.y;
        }
    }
}

// KSPLIT: build split-bf16 operands (coalesced writes, off the critical
// simulation path).
//  A[r][s] = g_R[s][r] (transpose), split hi/lo.  (65536 elements)
//  B[s][c] = g_X[s][c] (copy),      split hi/lo.  (131072 elements)
__global__ void __launch_bounds__(256) ksplit() {
    int idx = blockIdx.x * 256 + threadIdx.x;
    if (idx < MROWS * NSTEPS) {
        const int r = idx >> 4, s = idx & 15;
        const float f  = g_R[s][r];
        const __nv_bfloat16 h0 = __float2bfloat16_rn(f);
        g_A0[idx] = h0;
        g_A1[idx] = __float2bfloat16_rn(f - __bfloat162float(h0));
    } else {
        idx -= MROWS * NSTEPS;
        const float f  = (&g_X[0][0])[idx];
        const __nv_bfloat16 h0 = __float2bfloat16_rn(f);
        g_B0[idx] = h0;
        g_B1[idx] = __float2bfloat16_rn(f - __bfloat162float(h0));
    }
}

// K4: C[(i,a)][(n,b)] = sum_s A[(i,a)][s] * B[s][(n,b)]  — one 4096x8192x16
// GEMM via wmma 16x16x16 bf16, 3-pass split-bf16 (a0b0 + a0b1 + a1b0;
// dropped a1b1 ~ 2^-16 relative). Best-measured configuration (R12).
constexpr int ALD = 24;    // bf16 smem ldm for A (16 + 8 pad; mult of 8)
constexpr int BLD = 136;   // bf16 smem ldm for B (128 + 8 pad; mult of 8)

__global__ void __launch_bounds__(256) k4_jac(float* __restrict__ jac) {
    __shared__ __align__(16) __nv_bfloat16 sA0[128 * ALD];   // 6 KB
    __shared__ __align__(16) __nv_bfloat16 sA1[128 * ALD];
    __shared__ __align__(16) __nv_bfloat16 sB0[16 * BLD];    // 4.25 KB
    __shared__ __align__(16) __nv_bfloat16 sB1[16 * BLD];
    const int tid = threadIdx.x, bid = blockIdx.x;
    const int m0 = (bid & 31) * 128;   // 32 M-blocks
    const int n0 = (bid >> 5) * 128;   // 64 N-blocks

    // Stage A (128 rows x 16 bf16) and B (16 rows x 128 bf16), both splits.
    {
        const int row = tid >> 1, q = (tid & 1) << 3;
        *(float4*)&sA0[row * ALD + q] =
            *(const float4*)&g_A0[(size_t)(m0 + row) * NSTEPS + q];
        *(float4*)&sA1[row * ALD + q] =
            *(const float4*)&g_A1[(size_t)(m0 + row) * NSTEPS + q];
        const int s = tid >> 4, bq = (tid & 15) << 3;
        *(float4*)&sB0[s * BLD + bq] =
            *(const float4*)&g_B0[(size_t)s * NCOLS + n0 + bq];
        *(float4*)&sB1[s * BLD + bq] =
            *(const float4*)&g_B1[(size_t)s * NCOLS + n0 + bq];
    }
    __syncthreads();

    const int wid = tid >> 5;
    const int wm = wid & 3, wn = wid >> 2;

    wmma::fragment<wmma::matrix_a, 16, 16, 16, __nv_bfloat16,
                   wmma::row_major> a0f[2], a1f[2];
#pragma unroll
    for (int mt = 0; mt < 2; mt++) {
        const int ro = (wm * 32 + mt * 16) * ALD;
        wmma::load_matrix_sync(a0f[mt], &sA0[ro], ALD);
        wmma::load_matrix_sync(a1f[mt], &sA1[ro], ALD);
    }

#pragma unroll
    for (int nt = 0; nt < 4; nt++) {
        const int cl = wn * 64 + nt * 16;
        wmma::fragment<wmma::matrix_b, 16, 16, 16, __nv_bfloat16,
                       wmma::row_major> b0f, b1f;
        wmma::load_matrix_sync(b0f, &sB0[cl], BLD);
        wmma::load_matrix_sync(b1f, &sB1[cl], BLD);
#pragma unroll
        for (int mt = 0; mt < 2; mt++) {
            wmma::fragment<wmma::accumulator, 16, 16, 16, float> acc;
            wmma::fill_fragment(acc, 0.0f);
            wmma::mma_sync(acc, a0f[mt], b0f, acc);
            wmma::mma_sync(acc, a0f[mt], b1f, acc);
            wmma::mma_sync(acc, a1f[mt], b0f, acc);
            const int r = m0 + wm * 32 + mt * 16;   // (i,a)
            const int c = n0 + cl;                  // (n,b)
            // jac offset: ((n*64 + i)*64 + a)*64 + b
            const size_t off = (size_t)(c >> 6) * (64 * 64 * 64)
                             + (size_t)(r >> 6) * (64 * 64)
                             + (size_t)(r & 63) * 64
                             + (size_t)(c & 63);
            wmma::store_matrix_sync(jac + off, acc, 64, wmma::mem_row_major);
        }
    }
}

extern "C" void kernel_launch(void* const* d_in, const int* in_sizes, int n_in,
                              void* d_out, int out_size) {
    const float* x0 = (const float*)d_in[0];
    const float* v0 = (const float*)d_in[1];
    const float* W  = (const float*)d_in[2];
    float* out = (float*)d_out;
    // output = [traj (frames x N x D)] then [jac (N x D x D x D)]
    float* jac = out + ((size_t)out_size - (size_t)N * D * D * D);

    kprep<<<48, 128>>>(x0, v0, W, out);
    ksplit<<<(MROWS * NSTEPS + NSTEPS * NCOLS) / 256, 256>>>();
    k4_jac<<<2048, 256>>>(jac);
}

// round 16
// speedup vs baseline: 1.1039x; 1.0065x over previous
#include <cuda_runtime.h>
#include <cuda_bf16.h>
#include <mma.h>
#include <cstddef>
#include <cstdint>

using namespace nvcuda;

// Problem constants (fixed by setup_inputs)
constexpr int D      = 64;
constexpr int N      = 128;
constexpr int NSTEPS = 16;

constexpr int MROWS = D * D;       // 4096 = (i,a)
constexpr int NCOLS = N * D;       // 8192 = (n,b)

// ---------------- device scratch (no allocations allowed) ----------------
__device__ __align__(16) float g_RP[NSTEPS][D * D];  // [k][a*64+c] = Xp_k[a][c]
__device__ __align__(16) float g_X[NSTEPS][N * D];   // x_s, s = 0..15
// Split-bf16 operands (a ~= a0 + a1, 16 effective mantissa bits)
__device__ __align__(16) __nv_bfloat16 g_A0[MROWS * NSTEPS];   // A[r][s], r=(i,a)
__device__ __align__(16) __nv_bfloat16 g_A1[MROWS * NSTEPS];
__device__ __align__(16) __nv_bfloat16 g_B0[NSTEPS * NCOLS];   // B[s][c], c=(n,b)
__device__ __align__(16) __nv_bfloat16 g_B1[NSTEPS * NCOLS];

// KPREP: direct row-wise simulation of BOTH systems.
//   rows 0..127   : state rows (x0, v0)            -> g_X[t], traj frames
//   rows 128..191 : propagator rows a = row-128,
//                   X0 = dt^2*e_a, V0 = dt*e_a     -> g_RP[k] (ROW-major:
//                   coalesced float2 stores; the (i,a) transpose moves to
//                   ksplit, whose writes stay coalesced).
// W is staged TRANSPOSED in smem (coalesced fill) so the per-lane M-column
// register load is cheap LDS instead of 256B-stride scattered LDG (~1024
// L1 wavefronts per warp in the old version — the main kprep sink).
// One warp per row; lane owns 2 columns. M[k][c] = W[c][k] - delta(k,c).
__global__ void __launch_bounds__(128) kprep(const float* __restrict__ x0,
                                             const float* __restrict__ v0,
                                             const float* __restrict__ W,
                                             float* __restrict__ out) {
    __shared__ __align__(16) float sWt[64 * 66];   // sWt[k*66 + c] = W[c][k]
    __shared__ float sX[4][D];
    const int tid = threadIdx.x;
    const int w   = tid >> 5;                  // warp = local row
    const int l   = tid & 31;
    const int row = blockIdx.x * 4 + w;        // 0..191
    const int c0  = 2 * l;
    const float dt = 0.01f;
    const bool is_state = (row < N);
    const int a = row - N;

    // Coalesced W fill (reads W[c][k] linearly, writes transposed).
    for (int idx = tid; idx < D * D; idx += 128) {
        const int c = idx >> 6, k = idx & 63;
        sWt[k * 66 + c] = W[idx];
    }
    __syncthreads();

    // M columns c0, c0+1 into registers via conflict-free float2 LDS.
    float mA[D], mB[D];
#pragma unroll
    for (int k = 0; k < D; k++) {
        const float2 wv = *(const float2*)&sWt[k * 66 + c0];
        mA[k] = wv.x - (k == c0     ? 1.0f : 0.0f);
        mB[k] = wv.y - (k == c0 + 1 ? 1.0f : 0.0f);
    }

    float2 xl, vl;
    if (is_state) {
        xl = *(const float2*)(x0 + (size_t)row * D + c0);
        vl = *(const float2*)(v0 + (size_t)row * D + c0);
    } else {
        xl = make_float2(c0 == a ? dt * dt : 0.0f, (c0 + 1) == a ? dt * dt : 0.0f);
        vl = make_float2(c0 == a ? dt      : 0.0f, (c0 + 1) == a ? dt      : 0.0f);
    }

    // t = 0 outputs (all coalesced float2).
    if (is_state) {
        *(float2*)&g_X[0][row * D + c0] = xl;                 // x_0
        *(float2*)(out + (size_t)row * D + c0) = xl;          // traj frame 0
    } else {
        *(float2*)&g_RP[0][a * D + c0] = xl;                  // Xp_0 row a
    }

    *(float2*)&sX[w][c0] = xl;
    __syncwarp();

#pragma unroll 1
    for (int t = 1; t <= NSTEPS; t++) {
        float2 y0 = make_float2(0.0f, 0.0f);
        float2 y1 = make_float2(0.0f, 0.0f);
#pragma unroll
        for (int k = 0; k < D; k += 2) {
            const float2 xk = *(const float2*)&sX[w][k];
            y0.x += xk.x * mA[k];     y0.y += xk.x * mB[k];
            y1.x += xk.y * mA[k + 1]; y1.y += xk.y * mB[k + 1];
        }
        vl.x += dt * (y0.x + y1.x);  vl.y += dt * (y0.y + y1.y);
        xl.x += dt * vl.x;           xl.y += dt * vl.y;
        __syncwarp();
        *(float2*)&sX[w][c0] = xl;
        __syncwarp();

        if (is_state) {
            if (t < NSTEPS)
                *(float2*)&g_X[t][row * D + c0] = xl;
            if ((t & 3) == 0) {
                float* o = out + (size_t)(t >> 2) * NCOLS + (size_t)row * D + c0;
                *(float2*)o = xl;
            }
        } else if (t < NSTEPS) {
            *(float2*)&g_RP[t][a * D + c0] = xl;              // coalesced
        }
    }
}

// KSPLIT: build split-bf16 operands (coalesced writes; A-side reads do the
// (i,a) transpose as a gather — scattered reads from L2-resident g_RP).
//  A[r=(i,a)][s] = Xp_{15-s}[a][i] = g_RP[15-s][a*64 + i]   (65536 elements)
//  B[s][c]       = g_X[s][c]                                 (131072 elements)
__global__ void __launch_bounds__(256) ksplit() {
    int idx = blockIdx.x * 256 + threadIdx.x;
    if (idx < MROWS * NSTEPS) {
        const int r = idx >> 4, s = idx & 15;
        const int i = r >> 6, aa = r & 63;
        const float f  = g_RP[15 - s][aa * D + i];
        const __nv_bfloat16 h0 = __float2bfloat16_rn(f);
        g_A0[idx] = h0;
        g_A1[idx] = __float2bfloat16_rn(f - __bfloat162float(h0));
    } else {
        idx -= MROWS * NSTEPS;
        const float f  = (&g_X[0][0])[idx];
        const __nv_bfloat16 h0 = __float2bfloat16_rn(f);
        g_B0[idx] = h0;
        g_B1[idx] = __float2bfloat16_rn(f - __bfloat162float(h0));
    }
}

// K4: C[(i,a)][(n,b)] = sum_s A[(i,a)][s] * B[s][(n,b)]  — one 4096x8192x16
// GEMM via wmma 16x16x16 bf16, 3-pass split-bf16 (a0b0 + a0b1 + a1b0;
// dropped a1b1 ~ 2^-16 relative). Best-measured configuration (R12):
// regs 48 -> ~4-5 CTAs/SM; direct store_matrix_sync epilogue (smem-staged
// epilogues cost MORE L1 wavefronts and blow the register budget — R13).
constexpr int ALD = 24;    // bf16 smem ldm for A (16 + 8 pad; mult of 8)
constexpr int BLD = 136;   // bf16 smem ldm for B (128 + 8 pad; mult of 8)

__global__ void __launch_bounds__(256) k4_jac(float* __restrict__ jac) {
    __shared__ __align__(16) __nv_bfloat16 sA0[128 * ALD];   // 6 KB
    __shared__ __align__(16) __nv_bfloat16 sA1[128 * ALD];
    __shared__ __align__(16) __nv_bfloat16 sB0[16 * BLD];    // 4.25 KB
    __shared__ __align__(16) __nv_bfloat16 sB1[16 * BLD];
    const int tid = threadIdx.x, bid = blockIdx.x;
    const int m0 = (bid & 31) * 128;   // 32 M-blocks
    const int n0 = (bid >> 5) * 128;   // 64 N-blocks

    // Stage A (128 rows x 16 bf16) and B (16 rows x 128 bf16), both splits.
    {
        const int row = tid >> 1, q = (tid & 1) << 3;
        *(float4*)&sA0[row * ALD + q] =
            *(const float4*)&g_A0[(size_t)(m0 + row) * NSTEPS + q];
        *(float4*)&sA1[row * ALD + q] =
            *(const float4*)&g_A1[(size_t)(m0 + row) * NSTEPS + q];
        const int s = tid >> 4, bq = (tid & 15) << 3;
        *(float4*)&sB0[s * BLD + bq] =
            *(const float4*)&g_B0[(size_t)s * NCOLS + n0 + bq];
        *(float4*)&sB1[s * BLD + bq] =
            *(const float4*)&g_B1[(size_t)s * NCOLS + n0 + bq];
    }
    __syncthreads();

    const int wid = tid >> 5;
    const int wm = wid & 3, wn = wid >> 2;

    wmma::fragment<wmma::matrix_a, 16, 16, 16, __nv_bfloat16,
                   wmma::row_major> a0f[2], a1f[2];
#pragma unroll
    for (int mt = 0; mt < 2; mt++) {
        const int ro = (wm * 32 + mt * 16) * ALD;
        wmma::load_matrix_sync(a0f[mt], &sA0[ro], ALD);
        wmma::load_matrix_sync(a1f[mt], &sA1[ro], ALD);
    }

#pragma unroll
    for (int nt = 0; nt < 4; nt++) {
        const int cl = wn * 64 + nt * 16;
        wmma::fragment<wmma::matrix_b, 16, 16, 16, __nv_bfloat16,
                       wmma::row_major> b0f, b1f;
        wmma::load_matrix_sync(b0f, &sB0[cl], BLD);
        wmma::load_matrix_sync(b1f, &sB1[cl], BLD);
#pragma unroll
        for (int mt = 0; mt < 2; mt++) {
            wmma::fragment<wmma::accumulator, 16, 16, 16, float> acc;
            wmma::fill_fragment(acc, 0.0f);
            wmma::mma_sync(acc, a0f[mt], b0f, acc);
            wmma::mma_sync(acc, a0f[mt], b1f, acc);
            wmma::mma_sync(acc, a1f[mt], b0f, acc);
            const int r = m0 + wm * 32 + mt * 16;   // (i,a)
            const int c = n0 + cl;                  // (n,b)
            // jac offset: ((n*64 + i)*64 + a)*64 + b
            const size_t off = (size_t)(c >> 6) * (64 * 64 * 64)
                             + (size_t)(r >> 6) * (64 * 64)
                             + (size_t)(r & 63) * 64
                             + (size_t)(c & 63);
            wmma::store_matrix_sync(jac + off, acc, 64, wmma::mem_row_major);
        }
    }
}

extern "C" void kernel_launch(void* const* d_in, const int* in_sizes, int n_in,
                              void* d_out, int out_size) {
    const float* x0 = (const float*)d_in[0];
    const float* v0 = (const float*)d_in[1];
    const float* W  = (const float*)d_in[2];
    float* out = (float*)d_out;
    // output = [traj (frames x N x D)] then [jac (N x D x D x D)]
    float* jac = out + ((size_t)out_size - (size_t)N * D * D * D);

    kprep<<<48, 128>>>(x0, v0, W, out);
    ksplit<<<(MROWS * NSTEPS + NSTEPS * NCOLS) / 256, 256>>>();
    k4_jac<<<2048, 256>>>(jac);
}